// round 12
// baseline (speedup 1.0000x reference)
#include <cuda_runtime.h>
#include <cstdint>
#include <cstddef>

// ---------------- problem constants ----------------
#define SS 2048
#define BB 32
#define DD 256
#define HH 4
#define MM (SS * BB)           // 65536 rows
#define SBD (SS * BB * DD)     // 16,777,216 elements
#define EPSV 1e-5f

// ---------------- GEMM config ----------------
#define BLKM 128
#define BLKN 64
#define KCH 32
#define NCHUNK (DD / KCH)      // 8
#define SA 36                  // smem row stride (floats); LDS.128 conflict-free
#define A_FL (BLKM * SA)       // 4608 floats
#define B_FL (BLKN * SA)       // 2304 floats
#define STG_FL (A_FL + B_FL)   // 6912 floats = 27648 B per stage
#define NSTAGE 2
#define SMEM_BYTES (NSTAGE * STG_FL * 4)   // 55296 B -> 3 CTAs/SM

// ---------------- scratch (no cudaMalloc allowed) ----------------
__device__ float g_qa[SBD];
__device__ float g_qb[SBD];
__device__ float g_ka[SBD];
__device__ float g_kb[SBD];
__device__ float g_va[SBD];
__device__ float g_vb[SBD];
__device__ float g_w1[SBD];
__device__ float g_w2[SBD];
__device__ float g_wp[20 * DD * DD];     // preconverted tf32 (permuted) weights
__device__ float g_biasp[20 * DD];       // permuted biases
__device__ float g_stats8[8 * 512];
__device__ float g_scale[8 * 256];
__device__ float g_shift[8 * 256];
__device__ float g_xcat[BB * DD * HH];
__device__ float g_m0[BB * DD];
__device__ float g_m1[BB * DD];

// ---------------- helpers ----------------
__device__ __forceinline__ uint32_t smem_u32(const void* p)
{
    uint32_t a;
    asm("{ .reg .u64 t; cvta.to.shared.u64 t, %1; cvt.u32.u64 %0, t; }"
        : "=r"(a) : "l"(p));
    return a;
}

__device__ __forceinline__ uint32_t f2tf(float x)
{
    uint32_t r;
    asm("cvt.rna.tf32.f32 %0, %1;" : "=r"(r) : "f"(x));
    return r;
}
__device__ __forceinline__ float f2tff(float x)
{
    return __uint_as_float(f2tf(x));
}

// full 32-wide permutation: natural k -> stored pos = 8t + 2ks + half
__device__ __forceinline__ int permc32(int k)
{
    int k5 = k & 31;
    int t = k5 & 3, half = (k5 >> 2) & 1, ks = k5 >> 3;
    return (k & ~31) | (t * 8 + ks * 2 + half);
}
__device__ __forceinline__ int unpermc32(int p)
{
    int p5 = p & 31;
    int t = p5 >> 3, ks = (p5 & 7) >> 1, half = p5 & 1;
    return (p & ~31) | (ks * 8 + half * 4 + t);
}

__device__ __forceinline__ void mma_tf32(float* d, uint32_t a0, uint32_t a1,
                                         uint32_t a2, uint32_t a3,
                                         uint32_t b0, uint32_t b1)
{
    asm volatile(
        "mma.sync.aligned.m16n8k8.row.col.f32.tf32.tf32.f32 "
        "{%0,%1,%2,%3}, {%4,%5,%6,%7}, {%8,%9}, {%0,%1,%2,%3};"
        : "+f"(d[0]), "+f"(d[1]), "+f"(d[2]), "+f"(d[3])
        : "r"(a0), "r"(a1), "r"(a2), "r"(a3), "r"(b0), "r"(b1));
}

__device__ __forceinline__ void cpa16(uint32_t dst, const void* src)
{
    asm volatile("cp.async.cg.shared.global [%0], [%1], 16;"
                 :: "r"(dst), "l"(src));
}
#define CP_COMMIT() asm volatile("cp.async.commit_group;" ::: "memory")
#define CP_WAIT1()  asm volatile("cp.async.wait_group 1;" ::: "memory")

// ---------------- weight preprocessing: tf32 + permute ----------------
__global__ void prep_w(const float* __restrict__ wq, const float* __restrict__ wk,
                       const float* __restrict__ wv, const float* __restrict__ wl1,
                       const float* __restrict__ wl2,
                       const float* __restrict__ bq, const float* __restrict__ bk,
                       const float* __restrict__ bv, const float* __restrict__ bl1,
                       const float* __restrict__ bl2,
                       float* __restrict__ wp, float* __restrict__ biasp)
{
    const int m = blockIdx.y;
    const int row = blockIdx.x;
    const int col = threadIdx.x;
    const int h = m / 5, sel = m % 5;
    const float* W; const float* B;
    switch (sel) {
        case 0: W = wq; B = bq; break;
        case 1: W = wk; B = bk; break;
        case 2: W = wv; B = bv; break;
        case 3: W = wl1; B = bl1; break;
        default: W = wl2; B = bl2; break;
    }
    const float v = W[(size_t)h * DD * DD + (size_t)row * DD + col];
    const int prow = permc32(row);
    const int pcol = (h > 0 || sel >= 3) ? permc32(col) : col;
    wp[(size_t)m * DD * DD + (size_t)prow * DD + pcol] = __uint_as_float(f2tf(v));
    if (row == 0)
        biasp[m * DD + permc32(col)] = B[h * DD + col];
}

// ---------------- GEMM ----------------
// C[M,256] = act(A)[M,256] @ Wp^T + biasp (permuted channel space).
// Tile 128x64, 8 warps of 32x32, 3 CTAs/SM.
template<bool KPERM, bool CVTA, bool BN, bool WOUT, bool STATS, bool ROUND>
__global__ __launch_bounds__(256, 3) void gemm_tc(
    const float* __restrict__ A, const float* __restrict__ Wp,
    const float* __restrict__ bias, float* __restrict__ C,
    const float* __restrict__ trs, const float* __restrict__ trb,
    const float* __restrict__ sub, float* __restrict__ wout,
    float* __restrict__ stats)
{
    extern __shared__ float sm[];
    const uint32_t smb = smem_u32(sm);

    const int tid = threadIdx.x;
    const int wid = tid >> 5, lane = tid & 31;
    const int g = lane >> 2, t = lane & 3;
    const int wm = wid >> 1;        // 0..3 (32-row bands)
    const int wn = wid & 1;         // 0..1 (32-col bands)
    const int row0 = blockIdx.y * BLKM;
    const int col0 = blockIdx.x * BLKN;

    // fill mapping
    const int fr = tid >> 1, fk = (tid & 1) * 16;      // A: 128 rows x 32
    const int br = tid >> 2, bk = (tid & 3) * 8;       // B: 64 rows x 32
    const float* const aptr = A + (size_t)(row0 + fr) * DD + fk;
    const float* const wptr = Wp + (size_t)(col0 + br) * DD + bk;
    const uint32_t a_soff = (uint32_t)(fr * SA + fk) * 4u;
    const uint32_t b_soff = (uint32_t)(A_FL + br * SA + bk) * 4u;

    float acc[2][4][4];
#pragma unroll
    for (int mt = 0; mt < 2; mt++)
#pragma unroll
        for (int nt = 0; nt < 4; nt++)
#pragma unroll
            for (int j = 0; j < 4; j++) acc[mt][nt][j] = 0.f;

    // prologue: stage 0
    {
#pragma unroll
        for (int j = 0; j < 4; j++) cpa16(smb + a_soff + j * 16, aptr + j * 4);
#pragma unroll
        for (int j = 0; j < 2; j++) cpa16(smb + b_soff + j * 16, wptr + j * 4);
        CP_COMMIT();
    }

#pragma unroll 1
    for (int i = 0; i < NCHUNK; i++) {
        if (i + 1 < NCHUNK) {
            const uint32_t sb = smb + (uint32_t)(((i + 1) & 1) * STG_FL) * 4u;
            const float* ap = aptr + (i + 1) * KCH;
            const float* wp2 = wptr + (i + 1) * KCH;
#pragma unroll
            for (int j = 0; j < 4; j++) cpa16(sb + a_soff + j * 16, ap + j * 4);
#pragma unroll
            for (int j = 0; j < 2; j++) cpa16(sb + b_soff + j * 16, wp2 + j * 4);
        }
        CP_COMMIT();
        CP_WAIT1();
        __syncthreads();

        const float* Ab = sm + (i & 1) * STG_FL;
        const float* Bb = Ab + A_FL;

        if (KPERM) {
#pragma unroll
            for (int p = 0; p < 2; p++) {
                float4 sv, cv;
                if (BN) {
                    sv = *(const float4*)(trs + i * KCH + t * 8 + p * 4);
                    cv = *(const float4*)(trb + i * KCH + t * 8 + p * 4);
                }
                uint32_t af[2][8];
#pragma unroll
                for (int mt = 0; mt < 2; mt++) {
                    const float* ap = Ab + (wm * 32 + mt * 16 + g) * SA + t * 8 + p * 4;
                    float4 lo = *(const float4*)ap;
                    float4 hi = *(const float4*)(ap + 8 * SA);
                    if (BN) {
                        lo.x = fmaxf(fmaf(lo.x, sv.x, cv.x), 0.f);
                        lo.y = fmaxf(fmaf(lo.y, sv.y, cv.y), 0.f);
                        lo.z = fmaxf(fmaf(lo.z, sv.z, cv.z), 0.f);
                        lo.w = fmaxf(fmaf(lo.w, sv.w, cv.w), 0.f);
                        hi.x = fmaxf(fmaf(hi.x, sv.x, cv.x), 0.f);
                        hi.y = fmaxf(fmaf(hi.y, sv.y, cv.y), 0.f);
                        hi.z = fmaxf(fmaf(hi.z, sv.z, cv.z), 0.f);
                        hi.w = fmaxf(fmaf(hi.w, sv.w, cv.w), 0.f);
                    }
                    if (BN || CVTA) {
                        af[mt][0] = f2tf(lo.x); af[mt][1] = f2tf(hi.x);
                        af[mt][2] = f2tf(lo.y); af[mt][3] = f2tf(hi.y);
                        af[mt][4] = f2tf(lo.z); af[mt][5] = f2tf(hi.z);
                        af[mt][6] = f2tf(lo.w); af[mt][7] = f2tf(hi.w);
                    } else {
                        af[mt][0] = __float_as_uint(lo.x); af[mt][1] = __float_as_uint(hi.x);
                        af[mt][2] = __float_as_uint(lo.y); af[mt][3] = __float_as_uint(hi.y);
                        af[mt][4] = __float_as_uint(lo.z); af[mt][5] = __float_as_uint(hi.z);
                        af[mt][6] = __float_as_uint(lo.w); af[mt][7] = __float_as_uint(hi.w);
                    }
                }
                uint32_t bf[4][4];
#pragma unroll
                for (int nt = 0; nt < 4; nt++) {
                    const float* bp = Bb + (wn * 32 + nt * 8 + g) * SA + t * 8 + p * 4;
                    float4 b = *(const float4*)bp;
                    bf[nt][0] = __float_as_uint(b.x);
                    bf[nt][1] = __float_as_uint(b.y);
                    bf[nt][2] = __float_as_uint(b.z);
                    bf[nt][3] = __float_as_uint(b.w);
                }
#pragma unroll
                for (int mt = 0; mt < 2; mt++)
#pragma unroll
                    for (int nt = 0; nt < 4; nt++) {
                        mma_tf32(acc[mt][nt], af[mt][0], af[mt][1], af[mt][2],
                                 af[mt][3], bf[nt][0], bf[nt][1]);
                        mma_tf32(acc[mt][nt], af[mt][4], af[mt][5], af[mt][6],
                                 af[mt][7], bf[nt][2], bf[nt][3]);
                    }
            }
        } else {
#pragma unroll
            for (int ks = 0; ks < 4; ks++) {
                uint32_t af[2][4], bf[4][2];
#pragma unroll
                for (int mt = 0; mt < 2; mt++) {
                    const float* ap = Ab + (wm * 32 + mt * 16 + g) * SA + ks * 8;
                    af[mt][0] = f2tf(ap[t]);
                    af[mt][1] = f2tf(ap[8 * SA + t]);
                    af[mt][2] = f2tf(ap[t + 4]);
                    af[mt][3] = f2tf(ap[8 * SA + t + 4]);
                }
#pragma unroll
                for (int nt = 0; nt < 4; nt++) {
                    const float* bp = Bb + (wn * 32 + nt * 8 + g) * SA + ks * 8;
                    bf[nt][0] = __float_as_uint(bp[t]);
                    bf[nt][1] = __float_as_uint(bp[t + 4]);
                }
#pragma unroll
                for (int mt = 0; mt < 2; mt++)
#pragma unroll
                    for (int nt = 0; nt < 4; nt++)
                        mma_tf32(acc[mt][nt], af[mt][0], af[mt][1], af[mt][2],
                                 af[mt][3], bf[nt][0], bf[nt][1]);
            }
        }
        if (i + 1 < NCHUNK) __syncthreads();
    }

    // ---- epilogue ----
    float csum[8], csq[8];
    if (STATS) {
#pragma unroll
        for (int j = 0; j < 8; j++) { csum[j] = 0.f; csq[j] = 0.f; }
    }

#pragma unroll
    for (int mt = 0; mt < 2; mt++) {
        const int r = row0 + wm * 32 + mt * 16 + g;
#pragma unroll
        for (int nt = 0; nt < 4; nt++) {
            const int c = col0 + wn * 32 + nt * 8 + 2 * t;
            const float2 bi = *(const float2*)(bias + c);
            float2 o0, o1;
            o0.x = acc[mt][nt][0] + bi.x;
            o0.y = acc[mt][nt][1] + bi.y;
            o1.x = acc[mt][nt][2] + bi.x;
            o1.y = acc[mt][nt][3] + bi.y;
            if (ROUND) {
                o0.x = f2tff(o0.x); o0.y = f2tff(o0.y);
                o1.x = f2tff(o1.x); o1.y = f2tff(o1.y);
            }
            if (C != nullptr) {
                *(float2*)(C + (size_t)r * DD + c) = o0;
                *(float2*)(C + (size_t)(r + 8) * DD + c) = o1;
            }
            float2 v0 = o0, v1 = o1;
            if (WOUT) {
                float2 s0 = *(const float2*)(sub + (size_t)r * DD + c);
                float2 s1 = *(const float2*)(sub + (size_t)(r + 8) * DD + c);
                v0.x = o0.x - s0.x; v0.y = o0.y - s0.y;
                v1.x = o1.x - s1.x; v1.y = o1.y - s1.y;
                if (ROUND) {
                    v0.x = f2tff(v0.x); v0.y = f2tff(v0.y);
                    v1.x = f2tff(v1.x); v1.y = f2tff(v1.y);
                }
                *(float2*)(wout + (size_t)r * DD + c) = v0;
                *(float2*)(wout + (size_t)(r + 8) * DD + c) = v1;
            }
            if (STATS) {
                csum[nt * 2 + 0] += v0.x + v1.x;
                csum[nt * 2 + 1] += v0.y + v1.y;
                csq[nt * 2 + 0] += v0.x * v0.x + v1.x * v1.x;
                csq[nt * 2 + 1] += v0.y * v0.y + v1.y * v1.y;
            }
        }
    }

    if (STATS) {
#pragma unroll
        for (int j = 0; j < 8; j++) {
#pragma unroll
            for (int off = 4; off < 32; off <<= 1) {
                csum[j] += __shfl_xor_sync(0xFFFFFFFFu, csum[j], off);
                csq[j] += __shfl_xor_sync(0xFFFFFFFFu, csq[j], off);
            }
        }
        if (g == 0) {
#pragma unroll
            for (int nt = 0; nt < 4; nt++) {
#pragma unroll
                for (int j = 0; j < 2; j++) {
                    const int c = col0 + wn * 32 + nt * 8 + 2 * t + j;
                    atomicAdd(&stats[c], csum[nt * 2 + j]);
                    atomicAdd(&stats[256 + c], csq[nt * 2 + j]);
                }
            }
        }
    }
}

// ---------------- zero stats ----------------
__global__ void zero_stats_k(float* stats)
{
    stats[blockIdx.x * 512 + threadIdx.x] = 0.f;
}

// ---------------- BN finalize (permuted space) ----------------
__global__ void bn_finalize_k(const float* __restrict__ stats,
                              const float* __restrict__ gamma,
                              const float* __restrict__ beta,
                              float* __restrict__ scale, float* __restrict__ shift)
{
    const int p = threadIdx.x;
    const int c = unpermc32(p);
    const float invM = 1.0f / (float)MM;
    float mean = stats[p] * invM;
    float var = stats[256 + p] * invM - mean * mean;
    float sc = gamma[c] * rsqrtf(var + EPSV);
    scale[p] = sc;
    shift[p] = beta[c] - mean * sc;
}

// ---------------- fused softmax(seq) * v sum (permuted in, natural out) ----------------
__global__ __launch_bounds__(256) void softmax_wv_k(const float* __restrict__ w,
                                                    const float* __restrict__ v,
                                                    float* __restrict__ xcat, int head)
{
    const int c = blockIdx.x * 32 + threadIdx.x;
    const int ty = threadIdx.y;
    float m = -1e30f, l = 0.f, a = 0.f;
    for (int s = ty; s < SS; s += 8) {
        const size_t idx = (size_t)s * (BB * DD) + c;
        float x = w[idx];
        float val = v[idx];
        float nm = fmaxf(m, x);
        float corr = __expf(m - nm);
        float e = __expf(x - nm);
        l = l * corr + e;
        a = a * corr + e * val;
        m = nm;
    }
    __shared__ float sm_[8][32], sl[8][32], sa[8][32];
    sm_[ty][threadIdx.x] = m;
    sl[ty][threadIdx.x] = l;
    sa[ty][threadIdx.x] = a;
    __syncthreads();
    if (ty == 0) {
        for (int j = 1; j < 8; j++) {
            float m2 = sm_[j][threadIdx.x], l2 = sl[j][threadIdx.x], a2 = sa[j][threadIdx.x];
            float nm = fmaxf(m, m2);
            float c1 = __expf(m - nm), c2 = __expf(m2 - nm);
            l = l * c1 + l2 * c2;
            a = a * c1 + a2 * c2;
            m = nm;
        }
        const int b = c >> 8;
        const int d = unpermc32(c & 255);
        xcat[b * (DD * HH) + head * DD + d] = a / l;
    }
}

// ---------------- tiny final MLP layer ----------------
__global__ __launch_bounds__(256) void mlp_k(const float* __restrict__ x,
                                             const float* __restrict__ Wt,
                                             const float* __restrict__ bias,
                                             float* __restrict__ y, int K, int do_relu)
{
    __shared__ float xs[1024];
    const int b = blockIdx.x;
    for (int i = threadIdx.x; i < K; i += 256) xs[i] = x[b * K + i];
    __syncthreads();
    const int n = threadIdx.x;
    float acc = bias[n];
    const float* wr = Wt + (size_t)n * K;
    for (int k = 0; k < K; k++) acc = fmaf(xs[k], wr[k], acc);
    if (do_relu) acc = fmaxf(acc, 0.f);
    y[b * DD + n] = acc;
}

// ---------------- driver ----------------
static float* sym(const void* s)
{
    void* p = nullptr;
    cudaGetSymbolAddress(&p, (const void*)s);
    return (float*)p;
}

extern "C" void kernel_launch(void* const* d_in, const int* in_sizes, int n_in,
                              void* d_out, int out_size)
{
    (void)in_sizes; (void)n_in; (void)out_size;
    const float* q_in = (const float*)d_in[0];
    const float* k_in = (const float*)d_in[1];
    const float* v_in = (const float*)d_in[2];
    const float* wq = (const float*)d_in[3];
    const float* bq = (const float*)d_in[4];
    const float* wk = (const float*)d_in[5];
    const float* bk = (const float*)d_in[6];
    const float* wv = (const float*)d_in[7];
    const float* bv = (const float*)d_in[8];
    const float* g1 = (const float*)d_in[9];
    const float* be1 = (const float*)d_in[10];
    const float* wl1 = (const float*)d_in[11];
    const float* bl1 = (const float*)d_in[12];
    const float* g2 = (const float*)d_in[13];
    const float* be2 = (const float*)d_in[14];
    const float* wl2 = (const float*)d_in[15];
    const float* bl2 = (const float*)d_in[16];
    const float* mw0 = (const float*)d_in[17];
    const float* mb0 = (const float*)d_in[18];
    const float* mw1 = (const float*)d_in[19];
    const float* mb1 = (const float*)d_in[20];
    const float* mw2 = (const float*)d_in[21];
    const float* mb2 = (const float*)d_in[22];

    float* qa = sym(g_qa); float* qb = sym(g_qb);
    float* ka = sym(g_ka); float* kb = sym(g_kb);
    float* va = sym(g_va); float* vb = sym(g_vb);
    float* w1 = sym(g_w1); float* w2 = sym(g_w2);
    float* wp = sym(g_wp);
    float* biasp = sym(g_biasp);
    float* stats8 = sym(g_stats8);
    float* scale8 = sym(g_scale);
    float* shift8 = sym(g_shift);
    float* xcat = sym(g_xcat);
    float* m0 = sym(g_m0);
    float* m1 = sym(g_m1);

    auto* Gh0qv = gemm_tc<false, true, false, false, false, true>;
    auto* Gh0k  = gemm_tc<false, true, false, true, true, true>;
    auto* Gqv   = gemm_tc<true, false, false, false, false, true>;
    auto* Gk    = gemm_tc<true, false, false, true, true, true>;
    auto* Gl1   = gemm_tc<true, false, true, false, true, true>;
    auto* Gl2   = gemm_tc<true, false, true, false, false, false>;

    cudaFuncSetAttribute(Gh0qv, cudaFuncAttributeMaxDynamicSharedMemorySize, SMEM_BYTES);
    cudaFuncSetAttribute(Gh0k, cudaFuncAttributeMaxDynamicSharedMemorySize, SMEM_BYTES);
    cudaFuncSetAttribute(Gqv, cudaFuncAttributeMaxDynamicSharedMemorySize, SMEM_BYTES);
    cudaFuncSetAttribute(Gk, cudaFuncAttributeMaxDynamicSharedMemorySize, SMEM_BYTES);
    cudaFuncSetAttribute(Gl1, cudaFuncAttributeMaxDynamicSharedMemorySize, SMEM_BYTES);
    cudaFuncSetAttribute(Gl2, cudaFuncAttributeMaxDynamicSharedMemorySize, SMEM_BYTES);

    prep_w<<<dim3(DD, 20), DD>>>(wq, wk, wv, wl1, wl2, bq, bk, bv, bl1, bl2,
                                 wp, biasp);
    zero_stats_k<<<8, 512>>>(stats8);

    const dim3 gg(DD / BLKN, MM / BLKM);   // (4, 512) = 2048 CTAs
    const float* qs = q_in; const float* ks = k_in; const float* vs = v_in;
    float* qpp[2] = { qa, qb };
    float* kpp[2] = { ka, kb };
    float* vpp[2] = { va, vb };

    for (int h = 0; h < HH; h++) {
        float* qd = qpp[h & 1];
        float* kd = kpp[h & 1];
        float* vd = vpp[h & 1];
        const int mq = h * 5 + 0, mk = h * 5 + 1, mv = h * 5 + 2;
        const int ml1 = h * 5 + 3, ml2 = h * 5 + 4;
        const float* Wq = wp + (size_t)mq * DD * DD;
        const float* Wk = wp + (size_t)mk * DD * DD;
        const float* Wv = wp + (size_t)mv * DD * DD;
        const float* Wm1 = wp + (size_t)ml1 * DD * DD;
        const float* Wm2 = wp + (size_t)ml2 * DD * DD;
        float* st1 = stats8 + (size_t)(2 * h) * 512;
        float* st2 = stats8 + (size_t)(2 * h + 1) * 512;
        float* sc1 = scale8 + (size_t)(2 * h) * 256;
        float* sh1 = shift8 + (size_t)(2 * h) * 256;
        float* sc2 = scale8 + (size_t)(2 * h + 1) * 256;
        float* sh2 = shift8 + (size_t)(2 * h + 1) * 256;

        if (h == 0) {
            Gh0qv<<<gg, 256, SMEM_BYTES>>>(
                qs, Wq, biasp + mq * DD, qd, nullptr, nullptr, nullptr, nullptr,
                nullptr);
            Gh0qv<<<gg, 256, SMEM_BYTES>>>(
                vs, Wv, biasp + mv * DD, vd, nullptr, nullptr, nullptr, nullptr,
                nullptr);
            Gh0k<<<gg, 256, SMEM_BYTES>>>(
                ks, Wk, biasp + mk * DD, kd, nullptr, nullptr, qd, w1, st1);
        } else {
            Gqv<<<gg, 256, SMEM_BYTES>>>(
                qs, Wq, biasp + mq * DD, qd, nullptr, nullptr, nullptr, nullptr,
                nullptr);
            Gqv<<<gg, 256, SMEM_BYTES>>>(
                vs, Wv, biasp + mv * DD, vd, nullptr, nullptr, nullptr, nullptr,
                nullptr);
            Gk<<<gg, 256, SMEM_BYTES>>>(
                ks, Wk, biasp + mk * DD, (h == HH - 1) ? nullptr : kd,
                nullptr, nullptr, qd, w1, st1);
        }

        bn_finalize_k<<<1, 256>>>(st1, g1 + h * DD, be1 + h * DD, sc1, sh1);
        Gl1<<<gg, 256, SMEM_BYTES>>>(
            w1, Wm1, biasp + ml1 * DD, w2, sc1, sh1, nullptr, nullptr, st2);

        bn_finalize_k<<<1, 256>>>(st2, g2 + h * DD, be2 + h * DD, sc2, sh2);
        Gl2<<<gg, 256, SMEM_BYTES>>>(
            w2, Wm2, biasp + ml2 * DD, w1, sc2, sh2, nullptr, nullptr, nullptr);

        softmax_wv_k<<<256, dim3(32, 8)>>>(w1, vd, xcat, h);

        qs = qd; ks = kd; vs = vd;
    }

    mlp_k<<<BB, 256>>>(xcat, mw0, mb0, m0, DD * HH, 1);
    mlp_k<<<BB, 256>>>(m0, mw1, mb1, m1, DD, 1);
    mlp_k<<<BB, 256>>>(m1, mw2, mb2, (float*)d_out, DD, 0);
}

// round 15
// speedup vs baseline: 1.0596x; 1.0596x over previous
#include <cuda_runtime.h>
#include <cstdint>
#include <cstddef>

// ---------------- problem constants ----------------
#define SS 2048
#define BB 32
#define DD 256
#define HH 4
#define MM (SS * BB)           // 65536 rows
#define SBD (SS * BB * DD)     // 16,777,216 elements
#define EPSV 1e-5f

// ---------------- GEMM config (round-11 best: 128x128, 2 CTAs/SM, 3-stage) ----------------
#define BLKM 128
#define BLKN 128
#define KCH 32
#define NCHUNK (DD / KCH)      // 8
#define SA 36                  // smem row stride (floats); LDS.128 conflict-free
#define A_FL (BLKM * SA)       // 4608 floats
#define STG_FL (2 * A_FL)      // A + B per stage (9216 floats)
#define NSTAGE 3
#define BN_FL 512              // scale[256] + shift[256] at smem head
#define SMEM_BYTES ((BN_FL + NSTAGE * STG_FL) * 4)   // 112640 B -> 2 CTAs/SM

// ---------------- scratch (no cudaMalloc allowed) ----------------
__device__ float g_qa[SBD];
__device__ float g_qb[SBD];
__device__ float g_ka[SBD];
__device__ float g_kb[SBD];
__device__ float g_va[SBD];
__device__ float g_vb[SBD];
__device__ float g_w1[SBD];
__device__ float g_w2[SBD];
__device__ float g_wp[20 * DD * DD];     // preconverted tf32 (permuted) weights
__device__ float g_biasp[20 * DD];       // permuted biases
__device__ float g_stats8[8 * 512];
__device__ float g_xcat[BB * DD * HH];
__device__ float g_m0[BB * DD];
__device__ float g_m1[BB * DD];

// ---------------- helpers ----------------
__device__ __forceinline__ uint32_t smem_u32(const void* p)
{
    uint32_t a;
    asm("{ .reg .u64 t; cvta.to.shared.u64 t, %1; cvt.u32.u64 %0, t; }"
        : "=r"(a) : "l"(p));
    return a;
}

__device__ __forceinline__ uint32_t f2tf(float x)
{
    uint32_t r;
    asm("cvt.rna.tf32.f32 %0, %1;" : "=r"(r) : "f"(x));
    return r;
}
__device__ __forceinline__ float f2tff(float x)
{
    return __uint_as_float(f2tf(x));
}

// full 32-wide permutation: natural k -> stored pos = 8t + 2ks + half
__device__ __forceinline__ int permc32(int k)
{
    int k5 = k & 31;
    int t = k5 & 3, half = (k5 >> 2) & 1, ks = k5 >> 3;
    return (k & ~31) | (t * 8 + ks * 2 + half);
}
__device__ __forceinline__ int unpermc32(int p)
{
    int p5 = p & 31;
    int t = p5 >> 3, ks = (p5 & 7) >> 1, half = p5 & 1;
    return (p & ~31) | (ks * 8 + half * 4 + t);
}

__device__ __forceinline__ void mma_tf32(float* d, uint32_t a0, uint32_t a1,
                                         uint32_t a2, uint32_t a3,
                                         uint32_t b0, uint32_t b1)
{
    asm volatile(
        "mma.sync.aligned.m16n8k8.row.col.f32.tf32.tf32.f32 "
        "{%0,%1,%2,%3}, {%4,%5,%6,%7}, {%8,%9}, {%0,%1,%2,%3};"
        : "+f"(d[0]), "+f"(d[1]), "+f"(d[2]), "+f"(d[3])
        : "r"(a0), "r"(a1), "r"(a2), "r"(a3), "r"(b0), "r"(b1));
}

__device__ __forceinline__ void cpa16(uint32_t dst, const void* src)
{
    asm volatile("cp.async.cg.shared.global [%0], [%1], 16;"
                 :: "r"(dst), "l"(src));
}
#define CP_COMMIT() asm volatile("cp.async.commit_group;" ::: "memory")
#define CP_WAIT1()  asm volatile("cp.async.wait_group 1;" ::: "memory")

// ---------------- weight preprocessing: tf32 + permute ----------------
__global__ void prep_w(const float* __restrict__ wq, const float* __restrict__ wk,
                       const float* __restrict__ wv, const float* __restrict__ wl1,
                       const float* __restrict__ wl2,
                       const float* __restrict__ bq, const float* __restrict__ bk,
                       const float* __restrict__ bv, const float* __restrict__ bl1,
                       const float* __restrict__ bl2,
                       float* __restrict__ wp, float* __restrict__ biasp)
{
    const int m = blockIdx.y;
    const int row = blockIdx.x;
    const int col = threadIdx.x;
    const int h = m / 5, sel = m % 5;
    const float* W; const float* B;
    switch (sel) {
        case 0: W = wq; B = bq; break;
        case 1: W = wk; B = bk; break;
        case 2: W = wv; B = bv; break;
        case 3: W = wl1; B = bl1; break;
        default: W = wl2; B = bl2; break;
    }
    const float v = W[(size_t)h * DD * DD + (size_t)row * DD + col];
    const int prow = permc32(row);
    const int pcol = (h > 0 || sel >= 3) ? permc32(col) : col;
    wp[(size_t)m * DD * DD + (size_t)prow * DD + pcol] = __uint_as_float(f2tf(v));
    if (row == 0)
        biasp[m * DD + permc32(col)] = B[h * DD + col];
}

// ---------------- GEMM ----------------
// C[M,256] = act(A)[M,256] @ Wp^T + biasp (permuted channel space).
// blockIdx.z selects (A,W,bias,C) vs (A2,W2,bias2,C2)  [qv fusion].
// BN: scale/shift computed per-CTA from stats_in/gamma/beta into smem head,
//     applied as relu(a*s+c) on fragment load, then cvt to tf32.
// KPERM: smem k-order fully permuted -> LDS.128 fragment loads.
// CVTA: A raw fp32, cvt on fragment load. WOUT: wout = C - sub.
// STATS: column sum/sumsq atomics over (WOUT? wout : C). ROUND: tf32-round outputs.
template<bool KPERM, bool CVTA, bool BN, bool WOUT, bool STATS, bool ROUND>
__global__ __launch_bounds__(256, 2) void gemm_tc(
    const float* __restrict__ A, const float* __restrict__ A2,
    const float* __restrict__ Wp, const float* __restrict__ Wp2,
    const float* __restrict__ bias, const float* __restrict__ bias2,
    float* __restrict__ C, float* __restrict__ C2,
    const float* __restrict__ stats_in, const float* __restrict__ gamma,
    const float* __restrict__ beta,
    const float* __restrict__ sub, float* __restrict__ wout,
    float* __restrict__ stats_out)
{
    extern __shared__ float sm[];
    const uint32_t smb = smem_u32(sm);
    float* const smst = sm + BN_FL;           // stages after scale/shift
    const uint32_t smb_st = smb + BN_FL * 4u;

    const float* A_ = A;
    const float* W_ = Wp;
    const float* bias_ = bias;
    float* C_ = C;
    if (blockIdx.z == 1) { A_ = A2; W_ = Wp2; bias_ = bias2; C_ = C2; }

    const int tid = threadIdx.x;
    const int wid = tid >> 5, lane = tid & 31;
    const int g = lane >> 2, t = lane & 3;
    const int wm = wid >> 2;        // 0..1 (64-row bands)
    const int wn = wid & 3;         // 0..3 (32-col bands)
    const int row0 = blockIdx.y * BLKM;
    const int col0 = blockIdx.x * BLKN;

    // BN finalize into smem (read in mainloop after first __syncthreads)
    if (BN) {
        const int p = tid;
        const int c = unpermc32(p);
        const float invM = 1.0f / (float)MM;
        float mean = stats_in[p] * invM;
        float var = stats_in[256 + p] * invM - mean * mean;
        float sc = gamma[c] * rsqrtf(var + EPSV);
        sm[p] = sc;
        sm[256 + p] = beta[c] - mean * sc;
    }

    // fill mapping: thread -> one half-row of 16 floats
    const int fr = tid >> 1, fk = (tid & 1) * 16;
    const float* const aptr = A_ + (size_t)(row0 + fr) * DD + fk;
    const float* const wptr = W_ + (size_t)(col0 + fr) * DD + fk;
    const uint32_t a_soff = (uint32_t)(fr * SA + fk) * 4u;
    const uint32_t b_soff = (uint32_t)(A_FL + fr * SA + fk) * 4u;

    float acc[4][4][4];
#pragma unroll
    for (int mt = 0; mt < 4; mt++)
#pragma unroll
        for (int nt = 0; nt < 4; nt++)
#pragma unroll
            for (int j = 0; j < 4; j++) acc[mt][nt][j] = 0.f;

    // prologue: chunks 0,1 into stages 0,1
#pragma unroll
    for (int p = 0; p < 2; p++) {
        const uint32_t sb = smb_st + (uint32_t)(p * STG_FL) * 4u;
        const float* ap = aptr + p * KCH;
        const float* wp2 = wptr + p * KCH;
#pragma unroll
        for (int j = 0; j < 4; j++) cpa16(sb + a_soff + j * 16, ap + j * 4);
#pragma unroll
        for (int j = 0; j < 4; j++) cpa16(sb + b_soff + j * 16, wp2 + j * 4);
        CP_COMMIT();
    }

#pragma unroll 1
    for (int i = 0; i < NCHUNK; i++) {
        CP_WAIT1();
        __syncthreads();

        // prefetch chunk i+2 (distance 2)
        if (i + 2 < NCHUNK) {
            const uint32_t sb = smb_st + (uint32_t)(((i + 2) % NSTAGE) * STG_FL) * 4u;
            const float* ap = aptr + (i + 2) * KCH;
            const float* wp2 = wptr + (i + 2) * KCH;
#pragma unroll
            for (int j = 0; j < 4; j++) cpa16(sb + a_soff + j * 16, ap + j * 4);
#pragma unroll
            for (int j = 0; j < 4; j++) cpa16(sb + b_soff + j * 16, wp2 + j * 4);
        }
        CP_COMMIT();

        const float* Ab = smst + (i % NSTAGE) * STG_FL;
        const float* Bb = Ab + A_FL;

        if (KPERM) {
#pragma unroll
            for (int p = 0; p < 2; p++) {
                float4 sv, cv;
                if (BN) {
                    sv = *(const float4*)(sm + i * KCH + t * 8 + p * 4);
                    cv = *(const float4*)(sm + 256 + i * KCH + t * 8 + p * 4);
                }
                uint32_t af[4][8];
#pragma unroll
                for (int mt = 0; mt < 4; mt++) {
                    const float* ap = Ab + (wm * 64 + mt * 16 + g) * SA + t * 8 + p * 4;
                    float4 lo = *(const float4*)ap;
                    float4 hi = *(const float4*)(ap + 8 * SA);
                    if (BN) {
                        lo.x = fmaxf(fmaf(lo.x, sv.x, cv.x), 0.f);
                        lo.y = fmaxf(fmaf(lo.y, sv.y, cv.y), 0.f);
                        lo.z = fmaxf(fmaf(lo.z, sv.z, cv.z), 0.f);
                        lo.w = fmaxf(fmaf(lo.w, sv.w, cv.w), 0.f);
                        hi.x = fmaxf(fmaf(hi.x, sv.x, cv.x), 0.f);
                        hi.y = fmaxf(fmaf(hi.y, sv.y, cv.y), 0.f);
                        hi.z = fmaxf(fmaf(hi.z, sv.z, cv.z), 0.f);
                        hi.w = fmaxf(fmaf(hi.w, sv.w, cv.w), 0.f);
                    }
                    if (BN || CVTA) {
                        af[mt][0] = f2tf(lo.x); af[mt][1] = f2tf(hi.x);
                        af[mt][2] = f2tf(lo.y); af[mt][3] = f2tf(hi.y);
                        af[mt][4] = f2tf(lo.z); af[mt][5] = f2tf(hi.z);
                        af[mt][6] = f2tf(lo.w); af[mt][7] = f2tf(hi.w);
                    } else {
                        af[mt][0] = __float_as_uint(lo.x); af[mt][1] = __float_as_uint(hi.x);
                        af[mt][2] = __float_as_uint(lo.y); af[mt][3] = __float_as_uint(hi.y);
                        af[mt][4] = __float_as_uint(lo.z); af[mt][5] = __float_as_uint(hi.z);
                        af[mt][6] = __float_as_uint(lo.w); af[mt][7] = __float_as_uint(hi.w);
                    }
                }
                uint32_t bf[4][4];
#pragma unroll
                for (int nt = 0; nt < 4; nt++) {
                    const float* bp = Bb + (wn * 32 + nt * 8 + g) * SA + t * 8 + p * 4;
                    float4 b = *(const float4*)bp;
                    bf[nt][0] = __float_as_uint(b.x);
                    bf[nt][1] = __float_as_uint(b.y);
                    bf[nt][2] = __float_as_uint(b.z);
                    bf[nt][3] = __float_as_uint(b.w);
                }
#pragma unroll
                for (int mt = 0; mt < 4; mt++)
#pragma unroll
                    for (int nt = 0; nt < 4; nt++) {
                        mma_tf32(acc[mt][nt], af[mt][0], af[mt][1], af[mt][2],
                                 af[mt][3], bf[nt][0], bf[nt][1]);
                        mma_tf32(acc[mt][nt], af[mt][4], af[mt][5], af[mt][6],
                                 af[mt][7], bf[nt][2], bf[nt][3]);
                    }
            }
        } else {
#pragma unroll
            for (int ks = 0; ks < 4; ks++) {
                uint32_t af[4][4], bf[4][2];
#pragma unroll
                for (int mt = 0; mt < 4; mt++) {
                    const float* ap = Ab + (wm * 64 + mt * 16 + g) * SA + ks * 8;
                    af[mt][0] = f2tf(ap[t]);
                    af[mt][1] = f2tf(ap[8 * SA + t]);
                    af[mt][2] = f2tf(ap[t + 4]);
                    af[mt][3] = f2tf(ap[8 * SA + t + 4]);
                }
#pragma unroll
                for (int nt = 0; nt < 4; nt++) {
                    const float* bp = Bb + (wn * 32 + nt * 8 + g) * SA + ks * 8;
                    bf[nt][0] = __float_as_uint(bp[t]);
                    bf[nt][1] = __float_as_uint(bp[t + 4]);
                }
#pragma unroll
                for (int mt = 0; mt < 4; mt++)
#pragma unroll
                    for (int nt = 0; nt < 4; nt++)
                        mma_tf32(acc[mt][nt], af[mt][0], af[mt][1], af[mt][2],
                                 af[mt][3], bf[nt][0], bf[nt][1]);
            }
        }
    }

    // ---- epilogue ----
    float csum[8], csq[8];
    if (STATS) {
#pragma unroll
        for (int j = 0; j < 8; j++) { csum[j] = 0.f; csq[j] = 0.f; }
    }

#pragma unroll
    for (int mt = 0; mt < 4; mt++) {
        const int r = row0 + wm * 64 + mt * 16 + g;
#pragma unroll
        for (int nt = 0; nt < 4; nt++) {
            const int c = col0 + wn * 32 + nt * 8 + 2 * t;
            const float2 bi = *(const float2*)(bias_ + c);
            float2 o0, o1;
            o0.x = acc[mt][nt][0] + bi.x;
            o0.y = acc[mt][nt][1] + bi.y;
            o1.x = acc[mt][nt][2] + bi.x;
            o1.y = acc[mt][nt][3] + bi.y;
            if (ROUND) {
                o0.x = f2tff(o0.x); o0.y = f2tff(o0.y);
                o1.x = f2tff(o1.x); o1.y = f2tff(o1.y);
            }
            if (C_ != nullptr) {
                *(float2*)(C_ + (size_t)r * DD + c) = o0;
                *(float2*)(C_ + (size_t)(r + 8) * DD + c) = o1;
            }
            float2 v0 = o0, v1 = o1;
            if (WOUT) {
                float2 s0 = *(const float2*)(sub + (size_t)r * DD + c);
                float2 s1 = *(const float2*)(sub + (size_t)(r + 8) * DD + c);
                v0.x = o0.x - s0.x; v0.y = o0.y - s0.y;
                v1.x = o1.x - s1.x; v1.y = o1.y - s1.y;
                if (ROUND) {
                    v0.x = f2tff(v0.x); v0.y = f2tff(v0.y);
                    v1.x = f2tff(v1.x); v1.y = f2tff(v1.y);
                }
                *(float2*)(wout + (size_t)r * DD + c) = v0;
                *(float2*)(wout + (size_t)(r + 8) * DD + c) = v1;
            }
            if (STATS) {
                csum[nt * 2 + 0] += v0.x + v1.x;
                csum[nt * 2 + 1] += v0.y + v1.y;
                csq[nt * 2 + 0] += v0.x * v0.x + v1.x * v1.x;
                csq[nt * 2 + 1] += v0.y * v0.y + v1.y * v1.y;
            }
        }
    }

    if (STATS) {
#pragma unroll
        for (int j = 0; j < 8; j++) {
#pragma unroll
            for (int off = 4; off < 32; off <<= 1) {
                csum[j] += __shfl_xor_sync(0xFFFFFFFFu, csum[j], off);
                csq[j] += __shfl_xor_sync(0xFFFFFFFFu, csq[j], off);
            }
        }
        if (g == 0) {
#pragma unroll
            for (int nt = 0; nt < 4; nt++) {
#pragma unroll
                for (int j = 0; j < 2; j++) {
                    const int c = col0 + wn * 32 + nt * 8 + 2 * t + j;
                    atomicAdd(&stats_out[c], csum[nt * 2 + j]);
                    atomicAdd(&stats_out[256 + c], csq[nt * 2 + j]);
                }
            }
        }
    }
}

// ---------------- zero stats ----------------
__global__ void zero_stats_k(float* stats)
{
    stats[blockIdx.x * 512 + threadIdx.x] = 0.f;
}

// ---------------- fused softmax(seq) * v sum (permuted in, natural out) ----------------
__global__ __launch_bounds__(256) void softmax_wv_k(const float* __restrict__ w,
                                                    const float* __restrict__ v,
                                                    float* __restrict__ xcat, int head)
{
    const int c = blockIdx.x * 32 + threadIdx.x;
    const int ty = threadIdx.y;
    float m = -1e30f, l = 0.f, a = 0.f;
    for (int s = ty; s < SS; s += 8) {
        const size_t idx = (size_t)s * (BB * DD) + c;
        float x = w[idx];
        float val = v[idx];
        float nm = fmaxf(m, x);
        float corr = __expf(m - nm);
        float e = __expf(x - nm);
        l = l * corr + e;
        a = a * corr + e * val;
        m = nm;
    }
    __shared__ float sm_[8][32], sl[8][32], sa[8][32];
    sm_[ty][threadIdx.x] = m;
    sl[ty][threadIdx.x] = l;
    sa[ty][threadIdx.x] = a;
    __syncthreads();
    if (ty == 0) {
        for (int j = 1; j < 8; j++) {
            float m2 = sm_[j][threadIdx.x], l2 = sl[j][threadIdx.x], a2 = sa[j][threadIdx.x];
            float nm = fmaxf(m, m2);
            float c1 = __expf(m - nm), c2 = __expf(m2 - nm);
            l = l * c1 + l2 * c2;
            a = a * c1 + a2 * c2;
            m = nm;
        }
        const int b = c >> 8;
        const int d = unpermc32(c & 255);
        xcat[b * (DD * HH) + head * DD + d] = a / l;
    }
}

// ---------------- tiny final MLP layer ----------------
__global__ __launch_bounds__(256) void mlp_k(const float* __restrict__ x,
                                             const float* __restrict__ Wt,
                                             const float* __restrict__ bias,
                                             float* __restrict__ y, int K, int do_relu)
{
    __shared__ float xs[1024];
    const int b = blockIdx.x;
    for (int i = threadIdx.x; i < K; i += 256) xs[i] = x[b * K + i];
    __syncthreads();
    const int n = threadIdx.x;
    float acc = bias[n];
    const float* wr = Wt + (size_t)n * K;
    for (int k = 0; k < K; k++) acc = fmaf(xs[k], wr[k], acc);
    if (do_relu) acc = fmaxf(acc, 0.f);
    y[b * DD + n] = acc;
}

// ---------------- driver ----------------
static float* sym(const void* s)
{
    void* p = nullptr;
    cudaGetSymbolAddress(&p, (const void*)s);
    return (float*)p;
}

extern "C" void kernel_launch(void* const* d_in, const int* in_sizes, int n_in,
                              void* d_out, int out_size)
{
    (void)in_sizes; (void)n_in; (void)out_size;
    const float* q_in = (const float*)d_in[0];
    const float* k_in = (const float*)d_in[1];
    const float* v_in = (const float*)d_in[2];
    const float* wq = (const float*)d_in[3];
    const float* bq = (const float*)d_in[4];
    const float* wk = (const float*)d_in[5];
    const float* bk = (const float*)d_in[6];
    const float* wv = (const float*)d_in[7];
    const float* bv = (const float*)d_in[8];
    const float* g1 = (const float*)d_in[9];
    const float* be1 = (const float*)d_in[10];
    const float* wl1 = (const float*)d_in[11];
    const float* bl1 = (const float*)d_in[12];
    const float* g2 = (const float*)d_in[13];
    const float* be2 = (const float*)d_in[14];
    const float* wl2 = (const float*)d_in[15];
    const float* bl2 = (const float*)d_in[16];
    const float* mw0 = (const float*)d_in[17];
    const float* mb0 = (const float*)d_in[18];
    const float* mw1 = (const float*)d_in[19];
    const float* mb1 = (const float*)d_in[20];
    const float* mw2 = (const float*)d_in[21];
    const float* mb2 = (const float*)d_in[22];

    float* qa = sym(g_qa); float* qb = sym(g_qb);
    float* ka = sym(g_ka); float* kb = sym(g_kb);
    float* va = sym(g_va); float* vb = sym(g_vb);
    float* w1 = sym(g_w1); float* w2 = sym(g_w2);
    float* wp = sym(g_wp);
    float* biasp = sym(g_biasp);
    float* stats8 = sym(g_stats8);
    float* xcat = sym(g_xcat);
    float* m0 = sym(g_m0);
    float* m1 = sym(g_m1);

    auto* Gh0qv = gemm_tc<false, true, false, false, false, true>;
    auto* Gh0k  = gemm_tc<false, true, false, true, true, true>;
    auto* Gqv   = gemm_tc<true, false, false, false, false, true>;
    auto* Gk    = gemm_tc<true, false, false, true, true, true>;
    auto* Gl1   = gemm_tc<true, false, true, false, true, true>;
    auto* Gl2   = gemm_tc<true, false, true, false, false, false>;

    cudaFuncSetAttribute(Gh0qv, cudaFuncAttributeMaxDynamicSharedMemorySize, SMEM_BYTES);
    cudaFuncSetAttribute(Gh0k, cudaFuncAttributeMaxDynamicSharedMemorySize, SMEM_BYTES);
    cudaFuncSetAttribute(Gqv, cudaFuncAttributeMaxDynamicSharedMemorySize, SMEM_BYTES);
    cudaFuncSetAttribute(Gk, cudaFuncAttributeMaxDynamicSharedMemorySize, SMEM_BYTES);
    cudaFuncSetAttribute(Gl1, cudaFuncAttributeMaxDynamicSharedMemorySize, SMEM_BYTES);
    cudaFuncSetAttribute(Gl2, cudaFuncAttributeMaxDynamicSharedMemorySize, SMEM_BYTES);

    prep_w<<<dim3(DD, 20), DD>>>(wq, wk, wv, wl1, wl2, bq, bk, bv, bl1, bl2,
                                 wp, biasp);
    zero_stats_k<<<8, 512>>>(stats8);

    const dim3 gg(DD / BLKN, MM / BLKM, 1);     // (2, 512)
    const dim3 gg2(DD / BLKN, MM / BLKM, 2);    // (2, 512, 2) fused q+v
    const float* qs = q_in; const float* ks = k_in; const float* vs = v_in;
    float* qpp[2] = { qa, qb };
    float* kpp[2] = { ka, kb };
    float* vpp[2] = { va, vb };

    for (int h = 0; h < HH; h++) {
        float* qd = qpp[h & 1];
        float* kd = kpp[h & 1];
        float* vd = vpp[h & 1];
        const int mq = h * 5 + 0, mk = h * 5 + 1, mv = h * 5 + 2;
        const int ml1 = h * 5 + 3, ml2 = h * 5 + 4;
        const float* Wq = wp + (size_t)mq * DD * DD;
        const float* Wk = wp + (size_t)mk * DD * DD;
        const float* Wv = wp + (size_t)mv * DD * DD;
        const float* Wm1 = wp + (size_t)ml1 * DD * DD;
        const float* Wm2 = wp + (size_t)ml2 * DD * DD;
        float* st1 = stats8 + (size_t)(2 * h) * 512;
        float* st2 = stats8 + (size_t)(2 * h + 1) * 512;

        if (h == 0) {
            // fused q+v projection (blockIdx.z picks set)
            Gh0qv<<<gg2, 256, SMEM_BYTES>>>(
                qs, vs, Wq, Wv, biasp + mq * DD, biasp + mv * DD, qd, vd,
                nullptr, nullptr, nullptr, nullptr, nullptr, nullptr);
            Gh0k<<<gg, 256, SMEM_BYTES>>>(
                ks, nullptr, Wk, nullptr, biasp + mk * DD, nullptr, kd, nullptr,
                nullptr, nullptr, nullptr, qd, w1, st1);
        } else {
            Gqv<<<gg2, 256, SMEM_BYTES>>>(
                qs, vs, Wq, Wv, biasp + mq * DD, biasp + mv * DD, qd, vd,
                nullptr, nullptr, nullptr, nullptr, nullptr, nullptr);
            Gk<<<gg, 256, SMEM_BYTES>>>(
                ks, nullptr, Wk, nullptr, biasp + mk * DD, nullptr,
                (h == HH - 1) ? nullptr : kd, nullptr,
                nullptr, nullptr, nullptr, qd, w1, st1);
        }

        // l1: BN1 finalize inlined (stats st1 + g1/be1), BN2 stats fused out
        Gl1<<<gg, 256, SMEM_BYTES>>>(
            w1, nullptr, Wm1, nullptr, biasp + ml1 * DD, nullptr, w2, nullptr,
            st1, g1 + h * DD, be1 + h * DD, nullptr, nullptr, st2);

        // l2: BN2 finalize inlined
        Gl2<<<gg, 256, SMEM_BYTES>>>(
            w2, nullptr, Wm2, nullptr, biasp + ml2 * DD, nullptr, w1, nullptr,
            st2, g2 + h * DD, be2 + h * DD, nullptr, nullptr, nullptr);

        softmax_wv_k<<<256, dim3(32, 8)>>>(w1, vd, xcat, h);

        qs = qd; ks = kd; vs = vd;
    }

    mlp_k<<<BB, 256>>>(xcat, mw0, mb0, m0, DD * HH, 1);
    mlp_k<<<BB, 256>>>(m0, mw1, mb1, m1, DD, 1);
    mlp_k<<<BB, 256>>>(m1, mw2, mb2, (float*)d_out, DD, 0);
}